// round 15
// baseline (speedup 1.0000x reference)
#include <cuda_runtime.h>
#include <cuda.h>
#include <cuda_bf16.h>
#include <cuda_fp16.h>
#include <cstdint>

#define BB      16384
#define IN_DIM  512
#define HH      512
#define KK      1024
#define NN      2048
#define TM      128
#define TN      128
#define TK      64
#define KCHUNKS 16
#define NSTAGE  3
#define NWARPS  8
#define CSZ     ((size_t)BB * HH)

#define SM_FULL0   0
#define SM_EMPTY0  64
#define SM_STAGE0  1024
#define A_OFF      0
#define B_OFF      16384
#define STAGE_BYTES 32768
#define SMEM_TOTAL (1024 + NSTAGE * STAGE_BYTES)
#define CHUNK_TX   32768u

#define ACT_BLOCKS (BB * IN_DIM / 8 / 256)   // 4096
#define W_BLOCKS   (NN * KK / 8 / 256)       // 1024

__device__ __align__(1024) __half g_Ah[(size_t)BB * KK];
__device__ __align__(1024) __half g_Bh[(size_t)NN * KK];
__device__ float g_bias[NN];

__device__ __forceinline__ uint32_t smem_u32(const void* p) {
    return (uint32_t)__cvta_generic_to_shared(p);
}
__device__ __forceinline__ void mbar_init(uint32_t a, uint32_t cnt) {
    asm volatile("mbarrier.init.shared.b64 [%0], %1;" :: "r"(a), "r"(cnt) : "memory");
}
__device__ __forceinline__ void mbar_arrive(uint32_t a) {
    asm volatile("mbarrier.arrive.release.cta.shared::cta.b64 _, [%0];" :: "r"(a) : "memory");
}
__device__ __forceinline__ void mbar_expect_tx(uint32_t a, uint32_t bytes) {
    asm volatile("mbarrier.arrive.expect_tx.shared.b64 _, [%0], %1;" :: "r"(a), "r"(bytes) : "memory");
}
__device__ __forceinline__ void mbar_wait(uint32_t a, uint32_t parity) {
    asm volatile(
        "{\n\t.reg .pred P1;\n\t"
        "LW_%=:\n\t"
        "mbarrier.try_wait.parity.acquire.cta.shared::cta.b64 P1, [%0], %1, 0x989680;\n\t"
        "@P1 bra.uni LD_%=;\n\t"
        "bra.uni LW_%=;\n\t"
        "LD_%=:\n\t}"
        :: "r"(a), "r"(parity) : "memory");
}
__device__ __forceinline__ void tma_load3d(uint32_t dst, const CUtensorMap* map,
                                           int cx_, int cy_, uint32_t mbar) {
    asm volatile(
        "cp.async.bulk.tensor.3d.shared::cta.global.tile.mbarrier::complete_tx::bytes "
        "[%0], [%1, {%2, %3, %4}], [%5];"
        :: "r"(dst), "l"(map), "r"(cx_), "r"(cy_), "r"(0), "r"(mbar) : "memory");
}
__device__ __forceinline__ void ldsm4(uint32_t* r, uint32_t addr) {
    asm volatile("ldmatrix.sync.aligned.m8n8.x4.shared.b16 {%0,%1,%2,%3}, [%4];"
        : "=r"(r[0]), "=r"(r[1]), "=r"(r[2]), "=r"(r[3]) : "r"(addr));
}
__device__ __forceinline__ void mma_f16(float* d, const uint32_t* a, uint32_t b0, uint32_t b1) {
    asm volatile("mma.sync.aligned.m16n8k16.row.col.f32.f16.f16.f32 "
        "{%0,%1,%2,%3}, {%4,%5,%6,%7}, {%8,%9}, {%0,%1,%2,%3};"
        : "+f"(d[0]), "+f"(d[1]), "+f"(d[2]), "+f"(d[3])
        : "r"(a[0]), "r"(a[1]), "r"(a[2]), "r"(a[3]), "r"(b0), "r"(b1));
}
__device__ __forceinline__ float sigf(float x) { return 1.0f / (1.0f + __expf(-x)); }
__device__ __forceinline__ float tanh_f(float x) {
    float e = __expf(2.0f * x);
    return 1.0f - 2.0f / (e + 1.0f);
}
__device__ __forceinline__ uint32_t pack_h2(float a, float b) {
    return (uint32_t)__half_as_ushort(__float2half_rn(a)) |
           ((uint32_t)__half_as_ushort(__float2half_rn(b)) << 16);
}
__device__ __forceinline__ uint4 pack_h8(float4 v0, float4 v1) {
    uint4 r;
    r.x = pack_h2(v0.x, v0.y);
    r.y = pack_h2(v0.z, v0.w);
    r.z = pack_h2(v1.x, v1.y);
    r.w = pack_h2(v1.z, v1.w);
    return r;
}

// merged prep, 8 elems/thread, 16B stores, loads batched before packing.
// W perm (TN=128, 4x2 warp grid, warp tile 32x64):
//   n = 128*ctaN + 64*wn + 8*j + 2*c + e
//   gate = 2*(j>>2)+e ; h = 32*ctaN + 16*wn + 4*(j&3) + c ; src = gate*512 + h
__global__ void prep_all(const float4* __restrict__ x4, const float4* __restrict__ hx4,
                         const float* __restrict__ Wx, const float* __restrict__ bx,
                         const float* __restrict__ Wh, const float* __restrict__ bh) {
    int b = blockIdx.x;
    if (b < ACT_BLOCKS) {
        int t = b * 256 + threadIdx.x;
        int m = t >> 6, k8 = (t & 63) << 3;
        size_t o = (size_t)m * KK + k8;
        // batch all 4 global loads first (MLP), then pack+store
        float4 xa = x4[2 * t], xb = x4[2 * t + 1];
        float4 ha = hx4[2 * t], hb_ = hx4[2 * t + 1];
        *reinterpret_cast<uint4*>(&g_Ah[o])       = pack_h8(xa, xb);
        *reinterpret_cast<uint4*>(&g_Ah[o + 512]) = pack_h8(ha, hb_);
    } else {
        int t = (b - ACT_BLOCKS) * 256 + threadIdx.x;
        int n = t >> 7, k8 = (t & 127) << 3;
        int ctaN = n >> 7, wn = (n >> 6) & 1, loc = n & 63;
        int j = loc >> 3, p = loc & 7, c = p >> 1, e = p & 1;
        int gate = ((j >> 2) << 1) | e;
        int h = ctaN * 32 + wn * 16 + 4 * (j & 3) + c;
        int src = gate * 512 + h;
        float4 v0, v1;
        if (k8 < 512) {
            const float4* w = (const float4*)(Wx + src * 512 + k8);
            v0 = w[0]; v1 = w[1];
        } else {
            const float4* w = (const float4*)(Wh + src * 512 + (k8 - 512));
            v0 = w[0]; v1 = w[1];
        }
        *reinterpret_cast<uint4*>(&g_Bh[(size_t)n * KK + k8]) = pack_h8(v0, v1);
        if (k8 == 0) g_bias[4 * h + gate] = bx[src] + bh[src];
    }
}

__global__ void __launch_bounds__(256, 2) lstm_fused(
    const __grid_constant__ CUtensorMap tmA,
    const __grid_constant__ CUtensorMap tmB,
    const float* __restrict__ cx,
    const float* __restrict__ w_ci,
    const float* __restrict__ w_cf,
    const float* __restrict__ w_co,
    float* __restrict__ out)
{
    extern __shared__ __align__(1024) char smem[];
    uint32_t sb = smem_u32(smem);
    int tid = threadIdx.x, wid = tid >> 5, lane = tid & 31;
    int warp_m = wid & 3, warp_n = wid >> 2;     // 4x2 warp grid; warp tile 32x64
    int tileN = blockIdx.x, tileM = blockIdx.y;

    if (tid == 0) {
        #pragma unroll
        for (int s = 0; s < NSTAGE; s++) {
            mbar_init(sb + SM_FULL0 + 8 * s, 1);
            mbar_init(sb + SM_EMPTY0 + 8 * s, NWARPS);
        }
        asm volatile("fence.proxy.async.shared::cta;" ::: "memory");
    }
    __syncthreads();

    if (tid == 0) {
        int mrow = tileM * TM, nrow = tileN * TN;
        #pragma unroll
        for (int s = 0; s < NSTAGE; s++) {
            uint32_t st = sb + SM_STAGE0 + s * STAGE_BYTES;
            uint32_t fb = sb + SM_FULL0 + 8 * s;
            mbar_expect_tx(fb, CHUNK_TX);
            tma_load3d(st + A_OFF, &tmA, s * TK, mrow, fb);
            tma_load3d(st + B_OFF, &tmB, s * TK, nrow, fb);
        }
    }

    uint32_t xb = (lane >> 4) << 4;
    uint32_t sw = (lane & 7) << 4;
    uint32_t rowoff_a = (uint32_t)(warp_m * 32 + (lane & 15)) * 128;
    uint32_t rowoff_b = (uint32_t)(warp_n * 64 + (lane & 15)) * 128;

    float acc[2][8][4] = {};

    for (int k = 0; k < KCHUNKS; k++) {
        int s = k % NSTAGE;
        uint32_t par = (uint32_t)((k / NSTAGE) & 1);
        mbar_wait(sb + SM_FULL0 + 8 * s, par);
        uint32_t stage = sb + SM_STAGE0 + s * STAGE_BYTES;
        uint32_t abase = stage + A_OFF + rowoff_a;
        uint32_t bbase = stage + B_OFF + rowoff_b;

        #pragma unroll
        for (int kk = 0; kk < 4; kk++) {
            uint32_t colo = ((uint32_t)(kk << 5) | xb) ^ sw;
            uint32_t a[2][4], b[4][4];
            #pragma unroll
            for (int mi = 0; mi < 2; mi++)
                ldsm4(a[mi], abase + mi * (16 * 128) + colo);
            #pragma unroll
            for (int bt = 0; bt < 4; bt++)
                ldsm4(b[bt], bbase + bt * (16 * 128) + colo);
            // slot logically free once the LAST ldsm of the chunk has executed:
            // arrive early so the producer can overlap refill with the final MMAs
            if (kk == 3 && lane == 0) mbar_arrive(sb + SM_EMPTY0 + 8 * s);
            #pragma unroll
            for (int bt = 0; bt < 4; bt++) {
                #pragma unroll
                for (int mi = 0; mi < 2; mi++) {
                    mma_f16(acc[mi][2*bt],   a[mi], b[bt][0], b[bt][2]);
                    mma_f16(acc[mi][2*bt+1], a[mi], b[bt][1], b[bt][3]);
                }
            }
        }
        // rotated producer: refill duty moves across warps chunk-by-chunk
        if (wid == (k & 7) && lane == 0 && k + NSTAGE < KCHUNKS) {
            mbar_wait(sb + SM_EMPTY0 + 8 * s, par);
            uint32_t st = sb + SM_STAGE0 + s * STAGE_BYTES;
            uint32_t fb = sb + SM_FULL0 + 8 * s;
            mbar_expect_tx(fb, CHUNK_TX);
            int kx = (k + NSTAGE) * TK;
            tma_load3d(st + A_OFF, &tmA, kx, tileM * TM, fb);
            tma_load3d(st + B_OFF, &tmB, kx, tileN * TN, fb);
        }
    }

    // ---- fused LSTM epilogue, pure registers, streaming stores ----
    int c = lane & 3;
    int hb = tileN * 32 + warp_n * 16 + c;
    float wci[4], wcf[4], wco[4];
    float4 bias[4];
    #pragma unroll
    for (int jj = 0; jj < 4; jj++) {
        int h = hb + 4 * jj;
        wci[jj] = w_ci[h]; wcf[jj] = w_cf[h]; wco[jj] = w_co[h];
        bias[jj] = *reinterpret_cast<const float4*>(&g_bias[4 * h]);
    }
    #pragma unroll
    for (int mi = 0; mi < 2; mi++) {
        #pragma unroll
        for (int half = 0; half < 2; half++) {
            int m = tileM * TM + warp_m * 32 + mi * 16 + half * 8 + (lane >> 2);
            const float* cxr = cx + (size_t)m * HH;
            float* hout = out + (size_t)m * HH;
            float* coutp = out + CSZ + (size_t)m * HH;
            #pragma unroll
            for (int jj = 0; jj < 4; jj++) {
                int h = hb + 4 * jj;
                float ip = acc[mi][jj][2*half+0]   + bias[jj].x;
                float fp = acc[mi][jj][2*half+1]   + bias[jj].y;
                float gp = acc[mi][jj+4][2*half+0] + bias[jj].z;
                float op = acc[mi][jj+4][2*half+1] + bias[jj].w;
                float c0 = __ldcs(&cxr[h]);
                float ig = sigf(ip + c0 * wci[jj]);
                float fg = sigf(fp + c0 * wcf[jj]);
                float gg = tanh_f(gp);
                float cn = fg * c0 + ig * gg;
                float og = sigf(op + cn * wco[jj]);
                __stcs(&hout[h], og * tanh_f(cn));
                __stcs(&coutp[h], cn);
            }
        }
    }
}

// ---------------- host ----------------
typedef CUresult (*tmap_fn)(CUtensorMap*, CUtensorMapDataType, cuuint32_t, void*,
                            const cuuint64_t*, const cuuint64_t*, const cuuint32_t*,
                            const cuuint32_t*, CUtensorMapInterleave, CUtensorMapSwizzle,
                            CUtensorMapL2promotion, CUtensorMapFloatOOBfill);

static void make_map(tmap_fn enc, CUtensorMap* m, void* ptr, uint64_t d0, uint64_t d1,
                     uint32_t b0, uint32_t b1) {
    cuuint64_t dims[3]    = {d0, d1, 1};
    cuuint64_t strides[2] = {d0 * 2, d0 * d1 * 2};
    cuuint32_t box[3]     = {b0, b1, 1};
    cuuint32_t es[3]      = {1, 1, 1};
    enc(m, CU_TENSOR_MAP_DATA_TYPE_FLOAT16, 3, ptr, dims, strides, box, es,
        CU_TENSOR_MAP_INTERLEAVE_NONE, CU_TENSOR_MAP_SWIZZLE_128B,
        CU_TENSOR_MAP_L2_PROMOTION_L2_128B, CU_TENSOR_MAP_FLOAT_OOB_FILL_NONE);
}

extern "C" void kernel_launch(void* const* d_in, const int* in_sizes, int n_in,
                              void* d_out, int out_size) {
    const float* x    = (const float*)d_in[0];
    const float* hx   = (const float*)d_in[1];
    const float* cx   = (const float*)d_in[2];
    const float* Wx   = (const float*)d_in[3];
    const float* bx   = (const float*)d_in[4];
    const float* Wh   = (const float*)d_in[5];
    const float* bh   = (const float*)d_in[6];
    const float* w_ci = (const float*)d_in[7];
    const float* w_cf = (const float*)d_in[8];
    const float* w_co = (const float*)d_in[9];
    float* out = (float*)d_out;

    tmap_fn enc = nullptr;
    cudaDriverEntryPointQueryResult qr;
    cudaGetDriverEntryPoint("cuTensorMapEncodeTiled", (void**)&enc, cudaEnableDefault, &qr);

    void *pA, *pB;
    cudaGetSymbolAddress(&pA, g_Ah);
    cudaGetSymbolAddress(&pB, g_Bh);

    CUtensorMap mA, mB;
    make_map(enc, &mA, pA, KK, BB, TK, TM);
    make_map(enc, &mB, pB, KK, NN, TK, TN);

    cudaFuncSetAttribute(lstm_fused, cudaFuncAttributeMaxDynamicSharedMemorySize, SMEM_TOTAL);

    prep_all<<<ACT_BLOCKS + W_BLOCKS, 256>>>((const float4*)x, (const float4*)hx,
                                             Wx, bx, Wh, bh);

    dim3 grid(NN / TN, BB / TM);
    lstm_fused<<<grid, 256, SMEM_TOTAL>>>(mA, mB, cx, w_ci, w_cf, w_co, out);
}

// round 16
// speedup vs baseline: 1.0635x; 1.0635x over previous
#include <cuda_runtime.h>
#include <cuda.h>
#include <cuda_bf16.h>
#include <cuda_fp16.h>
#include <cstdint>

#define BB      16384
#define IN_DIM  512
#define HH      512
#define KK      1024
#define NN      2048
#define TM      128
#define TN      128
#define TK      64
#define KCHUNKS 16
#define NSTAGE  3
#define NWARPS  8
#define CSZ     ((size_t)BB * HH)

#define SM_FULL0   0
#define SM_EMPTY0  64
#define SM_STAGE0  1024
#define A_OFF      0
#define B_OFF      16384
#define STAGE_BYTES 32768
#define SMEM_TOTAL (1024 + NSTAGE * STAGE_BYTES)
#define CHUNK_TX   32768u

#define ACT_BLOCKS (BB * IN_DIM / 8 / 256)   // 4096
#define W_BLOCKS   (NN * KK / 8 / 256)       // 1024

__device__ __align__(1024) __half g_Ah[(size_t)BB * KK];
__device__ __align__(1024) __half g_Bh[(size_t)NN * KK];
__device__ float g_bias[NN];

__device__ __forceinline__ uint32_t smem_u32(const void* p) {
    return (uint32_t)__cvta_generic_to_shared(p);
}
__device__ __forceinline__ void mbar_init(uint32_t a, uint32_t cnt) {
    asm volatile("mbarrier.init.shared.b64 [%0], %1;" :: "r"(a), "r"(cnt) : "memory");
}
__device__ __forceinline__ void mbar_arrive(uint32_t a) {
    asm volatile("mbarrier.arrive.release.cta.shared::cta.b64 _, [%0];" :: "r"(a) : "memory");
}
__device__ __forceinline__ void mbar_expect_tx(uint32_t a, uint32_t bytes) {
    asm volatile("mbarrier.arrive.expect_tx.shared.b64 _, [%0], %1;" :: "r"(a), "r"(bytes) : "memory");
}
__device__ __forceinline__ void mbar_wait(uint32_t a, uint32_t parity) {
    asm volatile(
        "{\n\t.reg .pred P1;\n\t"
        "LW_%=:\n\t"
        "mbarrier.try_wait.parity.acquire.cta.shared::cta.b64 P1, [%0], %1, 0x989680;\n\t"
        "@P1 bra.uni LD_%=;\n\t"
        "bra.uni LW_%=;\n\t"
        "LD_%=:\n\t}"
        :: "r"(a), "r"(parity) : "memory");
}
__device__ __forceinline__ void tma_load3d(uint32_t dst, const CUtensorMap* map,
                                           int cx_, int cy_, uint32_t mbar) {
    asm volatile(
        "cp.async.bulk.tensor.3d.shared::cta.global.tile.mbarrier::complete_tx::bytes "
        "[%0], [%1, {%2, %3, %4}], [%5];"
        :: "r"(dst), "l"(map), "r"(cx_), "r"(cy_), "r"(0), "r"(mbar) : "memory");
}
__device__ __forceinline__ void ldsm4(uint32_t* r, uint32_t addr) {
    asm volatile("ldmatrix.sync.aligned.m8n8.x4.shared.b16 {%0,%1,%2,%3}, [%4];"
        : "=r"(r[0]), "=r"(r[1]), "=r"(r[2]), "=r"(r[3]) : "r"(addr));
}
__device__ __forceinline__ void mma_f16(float* d, const uint32_t* a, uint32_t b0, uint32_t b1) {
    asm volatile("mma.sync.aligned.m16n8k16.row.col.f32.f16.f16.f32 "
        "{%0,%1,%2,%3}, {%4,%5,%6,%7}, {%8,%9}, {%0,%1,%2,%3};"
        : "+f"(d[0]), "+f"(d[1]), "+f"(d[2]), "+f"(d[3])
        : "r"(a[0]), "r"(a[1]), "r"(a[2]), "r"(a[3]), "r"(b0), "r"(b1));
}
__device__ __forceinline__ float sigf(float x) { return 1.0f / (1.0f + __expf(-x)); }
__device__ __forceinline__ float tanh_f(float x) {
    float e = __expf(2.0f * x);
    return 1.0f - 2.0f / (e + 1.0f);
}
__device__ __forceinline__ uint32_t pack_h2(float a, float b) {
    return (uint32_t)__half_as_ushort(__float2half_rn(a)) |
           ((uint32_t)__half_as_ushort(__float2half_rn(b)) << 16);
}
__device__ __forceinline__ uint4 pack_h8(float4 v0, float4 v1) {
    uint4 r;
    r.x = pack_h2(v0.x, v0.y);
    r.y = pack_h2(v0.z, v0.w);
    r.z = pack_h2(v1.x, v1.y);
    r.w = pack_h2(v1.z, v1.w);
    return r;
}

// merged prep, 8 elems/thread, 16B stores.
// W perm (TN=128, 4x2 warp grid, warp tile 32x64):
//   n = 128*ctaN + 64*wn + 8*j + 2*c + e
//   gate = 2*(j>>2)+e ; h = 32*ctaN + 16*wn + 4*(j&3) + c ; src = gate*512 + h
__global__ void prep_all(const float4* __restrict__ x4, const float4* __restrict__ hx4,
                         const float* __restrict__ Wx, const float* __restrict__ bx,
                         const float* __restrict__ Wh, const float* __restrict__ bh) {
    int b = blockIdx.x;
    if (b < ACT_BLOCKS) {
        int t = b * 256 + threadIdx.x;
        int m = t >> 6, k8 = (t & 63) << 3;
        size_t o = (size_t)m * KK + k8;
        float4 v0 = x4[2 * t], v1 = x4[2 * t + 1];
        *reinterpret_cast<uint4*>(&g_Ah[o]) = pack_h8(v0, v1);
        v0 = hx4[2 * t]; v1 = hx4[2 * t + 1];
        *reinterpret_cast<uint4*>(&g_Ah[o + 512]) = pack_h8(v0, v1);
    } else {
        int t = (b - ACT_BLOCKS) * 256 + threadIdx.x;
        int n = t >> 7, k8 = (t & 127) << 3;
        int ctaN = n >> 7, wn = (n >> 6) & 1, loc = n & 63;
        int j = loc >> 3, p = loc & 7, c = p >> 1, e = p & 1;
        int gate = ((j >> 2) << 1) | e;
        int h = ctaN * 32 + wn * 16 + 4 * (j & 3) + c;
        int src = gate * 512 + h;
        float4 v0, v1;
        if (k8 < 512) {
            const float4* w = (const float4*)(Wx + src * 512 + k8);
            v0 = w[0]; v1 = w[1];
        } else {
            const float4* w = (const float4*)(Wh + src * 512 + (k8 - 512));
            v0 = w[0]; v1 = w[1];
        }
        *reinterpret_cast<uint4*>(&g_Bh[(size_t)n * KK + k8]) = pack_h8(v0, v1);
        if (k8 == 0) g_bias[4 * h + gate] = bx[src] + bh[src];
    }
}

__global__ void __launch_bounds__(256, 2) lstm_fused(
    const __grid_constant__ CUtensorMap tmA,
    const __grid_constant__ CUtensorMap tmB,
    const float* __restrict__ cx,
    const float* __restrict__ w_ci,
    const float* __restrict__ w_cf,
    const float* __restrict__ w_co,
    float* __restrict__ out)
{
    extern __shared__ __align__(1024) char smem[];
    uint32_t sb = smem_u32(smem);
    int tid = threadIdx.x, wid = tid >> 5, lane = tid & 31;
    int warp_m = wid & 3, warp_n = wid >> 2;     // 4x2 warp grid; warp tile 32x64
    int tileN = blockIdx.x, tileM = blockIdx.y;

    if (tid == 0) {
        #pragma unroll
        for (int s = 0; s < NSTAGE; s++) {
            mbar_init(sb + SM_FULL0 + 8 * s, 1);
            mbar_init(sb + SM_EMPTY0 + 8 * s, NWARPS);
        }
        asm volatile("fence.proxy.async.shared::cta;" ::: "memory");
    }
    __syncthreads();

    if (tid == 0) {
        int mrow = tileM * TM, nrow = tileN * TN;
        #pragma unroll
        for (int s = 0; s < NSTAGE; s++) {
            uint32_t st = sb + SM_STAGE0 + s * STAGE_BYTES;
            uint32_t fb = sb + SM_FULL0 + 8 * s;
            mbar_expect_tx(fb, CHUNK_TX);
            tma_load3d(st + A_OFF, &tmA, s * TK, mrow, fb);
            tma_load3d(st + B_OFF, &tmB, s * TK, nrow, fb);
        }
    }

    uint32_t xb = (lane >> 4) << 4;
    uint32_t sw = (lane & 7) << 4;
    uint32_t rowoff_a = (uint32_t)(warp_m * 32 + (lane & 15)) * 128;
    uint32_t rowoff_b = (uint32_t)(warp_n * 64 + (lane & 15)) * 128;

    float acc[2][8][4] = {};

    for (int k = 0; k < KCHUNKS; k++) {
        int s = k % NSTAGE;
        uint32_t par = (uint32_t)((k / NSTAGE) & 1);
        mbar_wait(sb + SM_FULL0 + 8 * s, par);
        uint32_t stage = sb + SM_STAGE0 + s * STAGE_BYTES;
        uint32_t abase = stage + A_OFF + rowoff_a;
        uint32_t bbase = stage + B_OFF + rowoff_b;

        #pragma unroll
        for (int kk = 0; kk < 4; kk++) {
            uint32_t colo = ((uint32_t)(kk << 5) | xb) ^ sw;
            uint32_t a[2][4], b[4][4];
            #pragma unroll
            for (int mi = 0; mi < 2; mi++)
                ldsm4(a[mi], abase + mi * (16 * 128) + colo);
            #pragma unroll
            for (int bt = 0; bt < 4; bt++)
                ldsm4(b[bt], bbase + bt * (16 * 128) + colo);
            #pragma unroll
            for (int bt = 0; bt < 4; bt++) {
                #pragma unroll
                for (int mi = 0; mi < 2; mi++) {
                    mma_f16(acc[mi][2*bt],   a[mi], b[bt][0], b[bt][2]);
                    mma_f16(acc[mi][2*bt+1], a[mi], b[bt][1], b[bt][3]);
                }
            }
        }
        if (lane == 0) mbar_arrive(sb + SM_EMPTY0 + 8 * s);
        if (tid == 0 && k + NSTAGE < KCHUNKS) {
            mbar_wait(sb + SM_EMPTY0 + 8 * s, par);
            uint32_t st = sb + SM_STAGE0 + s * STAGE_BYTES;
            uint32_t fb = sb + SM_FULL0 + 8 * s;
            mbar_expect_tx(fb, CHUNK_TX);
            int kx = (k + NSTAGE) * TK;
            tma_load3d(st + A_OFF, &tmA, kx, tileM * TM, fb);
            tma_load3d(st + B_OFF, &tmB, kx, tileN * TN, fb);
        }
    }

    // ---- fused LSTM epilogue, pure registers ----
    int c = lane & 3;
    int hb = tileN * 32 + warp_n * 16 + c;
    float wci[4], wcf[4], wco[4];
    float4 bias[4];
    #pragma unroll
    for (int jj = 0; jj < 4; jj++) {
        int h = hb + 4 * jj;
        wci[jj] = w_ci[h]; wcf[jj] = w_cf[h]; wco[jj] = w_co[h];
        bias[jj] = *reinterpret_cast<const float4*>(&g_bias[4 * h]);
    }
    #pragma unroll
    for (int mi = 0; mi < 2; mi++) {
        #pragma unroll
        for (int half = 0; half < 2; half++) {
            int m = tileM * TM + warp_m * 32 + mi * 16 + half * 8 + (lane >> 2);
            const float* cxr = cx + (size_t)m * HH;
            float* hout = out + (size_t)m * HH;
            float* coutp = out + CSZ + (size_t)m * HH;
            #pragma unroll
            for (int jj = 0; jj < 4; jj++) {
                int h = hb + 4 * jj;
                float ip = acc[mi][jj][2*half+0]   + bias[jj].x;
                float fp = acc[mi][jj][2*half+1]   + bias[jj].y;
                float gp = acc[mi][jj+4][2*half+0] + bias[jj].z;
                float op = acc[mi][jj+4][2*half+1] + bias[jj].w;
                float c0 = cxr[h];
                float ig = sigf(ip + c0 * wci[jj]);
                float fg = sigf(fp + c0 * wcf[jj]);
                float gg = tanh_f(gp);
                float cn = fg * c0 + ig * gg;
                float og = sigf(op + cn * wco[jj]);
                hout[h] = og * tanh_f(cn);
                coutp[h] = cn;
            }
        }
    }
}

// ---------------- host ----------------
typedef CUresult (*tmap_fn)(CUtensorMap*, CUtensorMapDataType, cuuint32_t, void*,
                            const cuuint64_t*, const cuuint64_t*, const cuuint32_t*,
                            const cuuint32_t*, CUtensorMapInterleave, CUtensorMapSwizzle,
                            CUtensorMapL2promotion, CUtensorMapFloatOOBfill);

static void make_map(tmap_fn enc, CUtensorMap* m, void* ptr, uint64_t d0, uint64_t d1,
                     uint32_t b0, uint32_t b1) {
    cuuint64_t dims[3]    = {d0, d1, 1};
    cuuint64_t strides[2] = {d0 * 2, d0 * d1 * 2};
    cuuint32_t box[3]     = {b0, b1, 1};
    cuuint32_t es[3]      = {1, 1, 1};
    enc(m, CU_TENSOR_MAP_DATA_TYPE_FLOAT16, 3, ptr, dims, strides, box, es,
        CU_TENSOR_MAP_INTERLEAVE_NONE, CU_TENSOR_MAP_SWIZZLE_128B,
        CU_TENSOR_MAP_L2_PROMOTION_L2_128B, CU_TENSOR_MAP_FLOAT_OOB_FILL_NONE);
}

extern "C" void kernel_launch(void* const* d_in, const int* in_sizes, int n_in,
                              void* d_out, int out_size) {
    const float* x    = (const float*)d_in[0];
    const float* hx   = (const float*)d_in[1];
    const float* cx   = (const float*)d_in[2];
    const float* Wx   = (const float*)d_in[3];
    const float* bx   = (const float*)d_in[4];
    const float* Wh   = (const float*)d_in[5];
    const float* bh   = (const float*)d_in[6];
    const float* w_ci = (const float*)d_in[7];
    const float* w_cf = (const float*)d_in[8];
    const float* w_co = (const float*)d_in[9];
    float* out = (float*)d_out;

    tmap_fn enc = nullptr;
    cudaDriverEntryPointQueryResult qr;
    cudaGetDriverEntryPoint("cuTensorMapEncodeTiled", (void**)&enc, cudaEnableDefault, &qr);

    void *pA, *pB;
    cudaGetSymbolAddress(&pA, g_Ah);
    cudaGetSymbolAddress(&pB, g_Bh);

    CUtensorMap mA, mB;
    make_map(enc, &mA, pA, KK, BB, TK, TM);
    make_map(enc, &mB, pB, KK, NN, TK, TN);

    cudaFuncSetAttribute(lstm_fused, cudaFuncAttributeMaxDynamicSharedMemorySize, SMEM_TOTAL);

    prep_all<<<ACT_BLOCKS + W_BLOCKS, 256>>>((const float4*)x, (const float4*)hx,
                                             Wx, bx, Wh, bh);

    dim3 grid(NN / TN, BB / TM);
    lstm_fused<<<grid, 256, SMEM_TOTAL>>>(mA, mB, cx, w_ci, w_cf, w_co, out);
}